// round 1
// baseline (speedup 1.0000x reference)
#include <cuda_runtime.h>
#include <cuda_bf16.h>

#define HW   3136
#define CHW  802816
#define CDIM 256
#define MDIM 100352   // 32*3136
#define TS   36       // padded smem row stride (bf16 elems)

// -------- scratch (no cudaMalloc allowed) --------
__device__ float              g_y[(size_t)CDIM * MDIM];   // ~98 MB
__device__ unsigned char      g_k[(size_t)CDIM * MDIM];   // ~25 MB
__device__ unsigned long long g_csum[CDIM];
__device__ unsigned           g_yminK[CDIM];
__device__ unsigned           g_ymaxK[CDIM];
__device__ int                g_ksum[CDIM];
__device__ float              g_mn[CDIM], g_s[CDIM], g_dmin[CDIM], g_scale[CDIM], g_inv[CDIM], g_beta[CDIM];
__device__ __nv_bfloat16      g_uphi[CDIM * CDIM], g_uplo[CDIM * CDIM];

// -------- helpers --------
static __device__ __forceinline__ unsigned fkey(float f) {
    unsigned u = __float_as_uint(f);
    return (u & 0x80000000u) ? ~u : (u | 0x80000000u);
}
static __device__ __forceinline__ float kinv(unsigned k) {
    unsigned u = (k & 0x80000000u) ? (k & 0x7fffffffu) : ~k;
    return __uint_as_float(u);
}
static __device__ __forceinline__ void mma_bf16(float d[4], const unsigned a[4], const unsigned b[2]) {
    asm volatile(
        "mma.sync.aligned.m16n8k16.row.col.f32.bf16.bf16.f32 "
        "{%0,%1,%2,%3},{%4,%5,%6,%7},{%8,%9},{%0,%1,%2,%3};"
        : "+f"(d[0]), "+f"(d[1]), "+f"(d[2]), "+f"(d[3])
        : "r"(a[0]), "r"(a[1]), "r"(a[2]), "r"(a[3]), "r"(b[0]), "r"(b[1]));
}
static __device__ __forceinline__ void split_bf16(float v, __nv_bfloat16& hi, __nv_bfloat16& lo) {
    hi = __float2bfloat16(v);
    lo = __float2bfloat16(v - __bfloat162float(hi));
}

// -------- pass 0: reset scratch (re-run every replay) --------
__global__ void k_init() {
    int t = threadIdx.x;
    g_csum[t]  = 0ull;
    g_yminK[t] = 0xFFFFFFFFu;
    g_ymaxK[t] = 0u;
    g_ksum[t]  = 0;
}

// -------- pass 1: y = u^T @ relu(x); channel sums; per-row min/max of y --------
__global__ __launch_bounds__(256, 2) void k_gemm1(const float* __restrict__ x,
                                                  const float* __restrict__ u) {
    __shared__ __align__(16) __nv_bfloat16 Ah[128 * TS], Al[128 * TS];
    __shared__ __align__(16) __nv_bfloat16 Bh[128 * TS], Bl[128 * TS];
    __shared__ unsigned rmin[128], rmax[128];

    const int tid = threadIdx.x;
    const int cb  = blockIdx.x * 128;   // column base (pixel index)
    const int jb  = blockIdx.y * 128;   // output-row base (PCA dim)
    if (tid < 128) { rmin[tid] = 0xFFFFFFFFu; rmax[tid] = 0u; }

    const int warp = tid >> 5, lane = tid & 31;
    const int wj = (warp & 3) * 32;     // warp j-offset in tile
    const int wc = (warp >> 2) * 64;    // warp col-offset in tile

    float acc[2][8][4];
#pragma unroll
    for (int m = 0; m < 2; ++m)
#pragma unroll
        for (int nf = 0; nf < 8; ++nf)
#pragma unroll
            for (int q = 0; q < 4; ++q) acc[m][nf][q] = 0.f;

    for (int kc = 0; kc < 256; kc += 32) {
        // load A = u^T tile: A[j][c] = u[(kc+c)*256 + jb + j]
#pragma unroll
        for (int it = 0; it < 16; ++it) {
            int i = tid + it * 256;
            int c = i >> 7, j = i & 127;
            float v = u[(kc + c) * 256 + jb + j];
            split_bf16(v, Ah[j * TS + c], Al[j * TS + c]);
        }
        // load B = relu(x) tile: B[k=c][n=col] stored as Bs[col][c]
#pragma unroll
        for (int it = 0; it < 16; ++it) {
            int i = tid + it * 256;
            int c = i >> 7, col = i & 127;
            int gcol = cb + col;
            int n  = gcol / HW;
            int hw = gcol - n * HW;
            float v = x[(size_t)n * CHW + (size_t)(kc + c) * HW + hw];
            v = fmaxf(v, 0.f);
            split_bf16(v, Bh[col * TS + c], Bl[col * TS + c]);
        }
        __syncthreads();

        // channel sums of relu(x) (only j-tile 0 blocks; fixed-point, deterministic)
        if (blockIdx.y == 0) {
            int c = tid >> 3, part = tid & 7;
            float sgm = 0.f;
#pragma unroll
            for (int q = 0; q < 16; ++q) {
                int col = part * 16 + q;
                sgm += __bfloat162float(Bh[col * TS + c]) + __bfloat162float(Bl[col * TS + c]);
            }
            sgm += __shfl_down_sync(0xffffffffu, sgm, 4);
            sgm += __shfl_down_sync(0xffffffffu, sgm, 2);
            sgm += __shfl_down_sync(0xffffffffu, sgm, 1);
            if (part == 0)
                atomicAdd(&g_csum[kc + c], (unsigned long long)(long long)llrintf(sgm * 65536.f));
        }

#pragma unroll
        for (int ks = 0; ks < 2; ++ks) {
            const int kof = ks * 16;
            unsigned afh[2][4], afl[2][4];
#pragma unroll
            for (int m = 0; m < 2; ++m) {
                int r  = wj + m * 16 + (lane >> 2);
                int c0 = kof + (lane & 3) * 2;
                afh[m][0] = *(const unsigned*)&Ah[r * TS + c0];
                afh[m][1] = *(const unsigned*)&Ah[(r + 8) * TS + c0];
                afh[m][2] = *(const unsigned*)&Ah[r * TS + c0 + 8];
                afh[m][3] = *(const unsigned*)&Ah[(r + 8) * TS + c0 + 8];
                afl[m][0] = *(const unsigned*)&Al[r * TS + c0];
                afl[m][1] = *(const unsigned*)&Al[(r + 8) * TS + c0];
                afl[m][2] = *(const unsigned*)&Al[r * TS + c0 + 8];
                afl[m][3] = *(const unsigned*)&Al[(r + 8) * TS + c0 + 8];
            }
#pragma unroll
            for (int nf = 0; nf < 8; ++nf) {
                int coln = wc + nf * 8 + (lane >> 2);
                int k0   = kof + (lane & 3) * 2;
                unsigned bh[2], bl[2];
                bh[0] = *(const unsigned*)&Bh[coln * TS + k0];
                bh[1] = *(const unsigned*)&Bh[coln * TS + k0 + 8];
                bl[0] = *(const unsigned*)&Bl[coln * TS + k0];
                bl[1] = *(const unsigned*)&Bl[coln * TS + k0 + 8];
#pragma unroll
                for (int m = 0; m < 2; ++m) {
                    mma_bf16(acc[m][nf], afh[m], bh);  // hi*hi
                    mma_bf16(acc[m][nf], afh[m], bl);  // hi*lo
                    mma_bf16(acc[m][nf], afl[m], bh);  // lo*hi
                }
            }
        }
        __syncthreads();
    }

    // epilogue: per-row min/max into smem, store y
#pragma unroll
    for (int m = 0; m < 2; ++m) {
        float mn0 = 3.4e38f, mx0 = -3.4e38f, mn1 = 3.4e38f, mx1 = -3.4e38f;
#pragma unroll
        for (int nf = 0; nf < 8; ++nf) {
            mn0 = fminf(mn0, fminf(acc[m][nf][0], acc[m][nf][1]));
            mx0 = fmaxf(mx0, fmaxf(acc[m][nf][0], acc[m][nf][1]));
            mn1 = fminf(mn1, fminf(acc[m][nf][2], acc[m][nf][3]));
            mx1 = fmaxf(mx1, fmaxf(acc[m][nf][2], acc[m][nf][3]));
        }
        mn0 = fminf(mn0, __shfl_xor_sync(0xffffffffu, mn0, 1));
        mn0 = fminf(mn0, __shfl_xor_sync(0xffffffffu, mn0, 2));
        mx0 = fmaxf(mx0, __shfl_xor_sync(0xffffffffu, mx0, 1));
        mx0 = fmaxf(mx0, __shfl_xor_sync(0xffffffffu, mx0, 2));
        mn1 = fminf(mn1, __shfl_xor_sync(0xffffffffu, mn1, 1));
        mn1 = fminf(mn1, __shfl_xor_sync(0xffffffffu, mn1, 2));
        mx1 = fmaxf(mx1, __shfl_xor_sync(0xffffffffu, mx1, 1));
        mx1 = fmaxf(mx1, __shfl_xor_sync(0xffffffffu, mx1, 2));
        if ((lane & 3) == 0) {
            int r0 = wj + m * 16 + (lane >> 2);
            atomicMin(&rmin[r0], fkey(mn0));
            atomicMax(&rmax[r0], fkey(mx0));
            atomicMin(&rmin[r0 + 8], fkey(mn1));
            atomicMax(&rmax[r0 + 8], fkey(mx1));
        }
    }
#pragma unroll
    for (int m = 0; m < 2; ++m) {
        int r0 = wj + m * 16 + (lane >> 2);
#pragma unroll
        for (int nf = 0; nf < 8; ++nf) {
            int coln = cb + wc + nf * 8 + (lane & 3) * 2;
            *(float2*)&g_y[(size_t)(jb + r0) * MDIM + coln] =
                make_float2(acc[m][nf][0], acc[m][nf][1]);
            *(float2*)&g_y[(size_t)(jb + r0 + 8) * MDIM + coln] =
                make_float2(acc[m][nf][2], acc[m][nf][3]);
        }
    }
    __syncthreads();
    if (tid < 128) {
        atomicMin(&g_yminK[jb + tid], rmin[tid]);
        atomicMax(&g_ymaxK[jb + tid], rmax[tid]);
    }
}

// -------- pass 2: mn, s, dmin/scale --------
__global__ void k_prep(const float* __restrict__ u, const float* __restrict__ cl) {
    __shared__ float mn_s[256];
    int j = threadIdx.x;
    float mn = (float)(((double)g_csum[j] * (1.0 / 65536.0)) / (double)MDIM);
    mn_s[j] = mn;
    g_mn[j] = mn;
    __syncthreads();
    float s = 0.f;
    for (int c = 0; c < 256; ++c) s += u[c * 256 + j] * mn_s[c];
    g_s[j] = s;
    float ymin = kinv(g_yminK[j]) - s;
    float ymax = kinv(g_ymaxK[j]) - s;
    float c = cl[j];
    float dmin = fminf(fmaxf(ymin, -c), c);
    float dmax = fminf(fmaxf(ymax, -c), c);
    float rng = dmax - dmin;
    float scale = 255.f / ((rng == 0.f) ? 1.f : rng);
    g_dmin[j]  = dmin;
    g_scale[j] = scale;
    g_inv[j]   = 1.f / scale;
}

// -------- pass 3: k = round((clip(y-s)-dmin)*scale) as uint8; row sums --------
__global__ __launch_bounds__(256) void k_quant() {
    __shared__ int wsum[8];
    int j = blockIdx.y;
    float s = g_s[j], dmin = g_dmin[j], sc = g_scale[j];
    size_t base = (size_t)j * MDIM + (size_t)blockIdx.x * 1024 + threadIdx.x * 4;
    float4 y4 = *(const float4*)&g_y[base];
    int k0 = (int)fminf(fmaxf(rintf((y4.x - s - dmin) * sc), 0.f), 255.f);
    int k1 = (int)fminf(fmaxf(rintf((y4.y - s - dmin) * sc), 0.f), 255.f);
    int k2 = (int)fminf(fmaxf(rintf((y4.z - s - dmin) * sc), 0.f), 255.f);
    int k3 = (int)fminf(fmaxf(rintf((y4.w - s - dmin) * sc), 0.f), 255.f);
    uchar4 kv = make_uchar4((unsigned char)k0, (unsigned char)k1,
                            (unsigned char)k2, (unsigned char)k3);
    *(uchar4*)&g_k[base] = kv;
    int ks = k0 + k1 + k2 + k3;
#pragma unroll
    for (int off = 16; off > 0; off >>= 1) ks += __shfl_down_sync(0xffffffffu, ks, off);
    int lane = threadIdx.x & 31, warp = threadIdx.x >> 5;
    if (lane == 0) wsum[warp] = ks;
    __syncthreads();
    if (warp == 0) {
        int v = (lane < 8) ? wsum[lane] : 0;
#pragma unroll
        for (int off = 4; off > 0; off >>= 1) v += __shfl_down_sync(0xffffffffu, v, off);
        if (lane == 0) atomicAdd(&g_ksum[j], v);
    }
}

// -------- pass 4: u' = u*inv (bf16 hi/lo) and beta --------
__global__ void k_prep2(const float* __restrict__ u) {
    __shared__ float red[256];
    int i = blockIdx.x, j = threadIdx.x;
    float inv = g_inv[j];
    float v = u[i * 256 + j] * inv;
    split_bf16(v, g_uphi[i * 256 + j], g_uplo[i * 256 + j]);
    float meank = (float)g_ksum[j] / (float)MDIM;
    red[j] = v * meank;
    __syncthreads();
    for (int sN = 128; sN > 0; sN >>= 1) {
        if (j < sN) red[j] += red[j + sN];
        __syncthreads();
    }
    if (j == 0) g_beta[i] = g_mn[i] - red[0];
}

// -------- pass 5: out = u' @ k + beta (to NCHW layout) --------
__global__ __launch_bounds__(256, 2) void k_gemm2(float* __restrict__ out) {
    __shared__ __align__(16) __nv_bfloat16 Ah[128 * TS], Al[128 * TS], Bh[128 * TS];
    __shared__ float sbeta[128];

    const int tid = threadIdx.x;
    const int cb = blockIdx.x * 128;   // pixel column base
    const int ib = blockIdx.y * 128;   // output channel base
    if (tid < 128) sbeta[tid] = g_beta[ib + tid];

    const int warp = tid >> 5, lane = tid & 31;
    const int wj = (warp & 3) * 32;
    const int wc = (warp >> 2) * 64;

    float acc[2][8][4];
#pragma unroll
    for (int m = 0; m < 2; ++m)
#pragma unroll
        for (int nf = 0; nf < 8; ++nf)
#pragma unroll
            for (int q = 0; q < 4; ++q) acc[m][nf][q] = 0.f;

    for (int kc = 0; kc < 256; kc += 32) {
#pragma unroll
        for (int it = 0; it < 16; ++it) {
            int i = tid + it * 256;
            int ii = i >> 5, jj = i & 31;
            Ah[ii * TS + jj] = g_uphi[(ib + ii) * 256 + kc + jj];
            Al[ii * TS + jj] = g_uplo[(ib + ii) * 256 + kc + jj];
        }
#pragma unroll
        for (int it = 0; it < 4; ++it) {
            int i = tid + it * 256;
            int jj = i >> 5, cg = i & 31;
            uchar4 kv = *(const uchar4*)&g_k[(size_t)(kc + jj) * MDIM + cb + cg * 4];
            int colb = cg * 4;
            Bh[(colb + 0) * TS + jj] = __float2bfloat16((float)kv.x);
            Bh[(colb + 1) * TS + jj] = __float2bfloat16((float)kv.y);
            Bh[(colb + 2) * TS + jj] = __float2bfloat16((float)kv.z);
            Bh[(colb + 3) * TS + jj] = __float2bfloat16((float)kv.w);
        }
        __syncthreads();

#pragma unroll
        for (int ks = 0; ks < 2; ++ks) {
            const int kof = ks * 16;
            unsigned ah[2][4], al[2][4];
#pragma unroll
            for (int m = 0; m < 2; ++m) {
                int r  = wj + m * 16 + (lane >> 2);
                int c0 = kof + (lane & 3) * 2;
                ah[m][0] = *(const unsigned*)&Ah[r * TS + c0];
                ah[m][1] = *(const unsigned*)&Ah[(r + 8) * TS + c0];
                ah[m][2] = *(const unsigned*)&Ah[r * TS + c0 + 8];
                ah[m][3] = *(const unsigned*)&Ah[(r + 8) * TS + c0 + 8];
                al[m][0] = *(const unsigned*)&Al[r * TS + c0];
                al[m][1] = *(const unsigned*)&Al[(r + 8) * TS + c0];
                al[m][2] = *(const unsigned*)&Al[r * TS + c0 + 8];
                al[m][3] = *(const unsigned*)&Al[(r + 8) * TS + c0 + 8];
            }
#pragma unroll
            for (int nf = 0; nf < 8; ++nf) {
                int coln = wc + nf * 8 + (lane >> 2);
                int k0   = kof + (lane & 3) * 2;
                unsigned b[2];
                b[0] = *(const unsigned*)&Bh[coln * TS + k0];
                b[1] = *(const unsigned*)&Bh[coln * TS + k0 + 8];
#pragma unroll
                for (int m = 0; m < 2; ++m) {
                    mma_bf16(acc[m][nf], ah[m], b);
                    mma_bf16(acc[m][nf], al[m], b);
                }
            }
        }
        __syncthreads();
    }

#pragma unroll
    for (int m = 0; m < 2; ++m) {
        int rl0 = wj + m * 16 + (lane >> 2);
        int row0 = ib + rl0;
        float b0 = sbeta[rl0], b1 = sbeta[rl0 + 8];
#pragma unroll
        for (int nf = 0; nf < 8; ++nf) {
            int col = cb + wc + nf * 8 + (lane & 3) * 2;
            int n  = col / HW;
            int hw = col - n * HW;
            size_t o0 = (size_t)n * CHW + (size_t)row0 * HW + hw;
            size_t o1 = (size_t)n * CHW + (size_t)(row0 + 8) * HW + hw;
            *(float2*)&out[o0] = make_float2(acc[m][nf][0] + b0, acc[m][nf][1] + b0);
            *(float2*)&out[o1] = make_float2(acc[m][nf][2] + b1, acc[m][nf][3] + b1);
        }
    }
}

extern "C" void kernel_launch(void* const* d_in, const int* in_sizes, int n_in,
                              void* d_out, int out_size) {
    const float* x  = (const float*)d_in[0];
    const float* u  = (const float*)d_in[1];
    const float* cl = (const float*)d_in[2];
    float* out = (float*)d_out;

    k_init<<<1, 256>>>();
    k_gemm1<<<dim3(784, 2), 256>>>(x, u);
    k_prep<<<1, 256>>>(u, cl);
    k_quant<<<dim3(98, 256), 256>>>();
    k_prep2<<<256, 256>>>(u);
    k_gemm2<<<dim3(784, 2), 256>>>(out);
}

// round 3
// speedup vs baseline: 1.6593x; 1.6593x over previous
#include <cuda_runtime.h>
#include <cuda_bf16.h>
#include <cstdint>

#define HW   3136
#define CHW  802816
#define MDIM 100352   // 32*56*56

// ---------------- scratch (no cudaMalloc allowed) ----------------
__device__ float              g_y[(size_t)256 * MDIM];
__device__ unsigned char      g_k[(size_t)256 * MDIM];
__device__ unsigned long long g_csum[256];
__device__ unsigned           g_yminK[256];
__device__ unsigned           g_ymaxK[256];
__device__ int                g_ksum[256];
__device__ float g_mn[256], g_s[256], g_dmin[256], g_scale[256], g_inv[256], g_beta[256];
__device__ __nv_bfloat16 g_uphi[65536], g_uplo[65536];   // u' = u*inv  [i][j]
__device__ __nv_bfloat16 g_uthi[65536], g_utlo[65536];   // u^T         [j][c]

// ---------------- helpers ----------------
static __device__ __forceinline__ unsigned fkey(float f) {
    unsigned u = __float_as_uint(f);
    return (u & 0x80000000u) ? ~u : (u | 0x80000000u);
}
static __device__ __forceinline__ float kinv(unsigned k) {
    unsigned u = (k & 0x80000000u) ? (k & 0x7fffffffu) : ~k;
    return __uint_as_float(u);
}
static __device__ __forceinline__ void split_bf16(float v, __nv_bfloat16& hi, __nv_bfloat16& lo) {
    hi = __float2bfloat16(v);
    lo = __float2bfloat16(v - __bfloat162float(hi));
}
static __device__ __forceinline__ void mma_bf16(float d[4], const unsigned a[4], const unsigned b[2]) {
    asm volatile(
        "mma.sync.aligned.m16n8k16.row.col.f32.bf16.bf16.f32 "
        "{%0,%1,%2,%3},{%4,%5,%6,%7},{%8,%9},{%0,%1,%2,%3};"
        : "+f"(d[0]), "+f"(d[1]), "+f"(d[2]), "+f"(d[3])
        : "r"(a[0]), "r"(a[1]), "r"(a[2]), "r"(a[3]), "r"(b[0]), "r"(b[1]));
}
static __device__ __forceinline__ void cp16(uint32_t dst, const void* src) {
    asm volatile("cp.async.cg.shared.global [%0],[%1],16;" :: "r"(dst), "l"(src));
}
static __device__ __forceinline__ unsigned pack2(__nv_bfloat16 a, __nv_bfloat16 b) {
    return (unsigned)__bfloat16_as_ushort(a) | ((unsigned)__bfloat16_as_ushort(b) << 16);
}

// -------- pass 0: reset accumulators --------
__global__ void k_init() {
    int t = threadIdx.x;
    g_csum[t]  = 0ull;
    g_yminK[t] = 0xFFFFFFFFu;
    g_ymaxK[t] = 0u;
    g_ksum[t]  = 0;
}
// -------- pass 0b: u^T hi/lo split, K-major [j][c] --------
__global__ void k_prep0(const float* __restrict__ u) {
    int j = blockIdx.x, c = threadIdx.x;
    float v = u[c * 256 + j];
    split_bf16(v, g_uthi[j * 256 + c], g_utlo[j * 256 + c]);
}

// ==================== GEMM1: y = u^T @ relu(x) ====================
// CTA: M=256 (all j), N=128 px, K=256 in 8 chunks of 32. 512 threads = 16 warps.
// smem: sc[256] | rmn[256] | rmx[256] | 2 buffers of (Ah 20480 | Al 20480 | Bh 9216 | Bl 9216)
#define G1_BUF 59392
__global__ __launch_bounds__(512, 1) void k_gemm1(const float* __restrict__ x) {
    extern __shared__ __align__(16) char smem[];
    int*      sc  = (int*)smem;
    unsigned* rmn = (unsigned*)(smem + 1024);
    unsigned* rmx = (unsigned*)(smem + 2048);
    char*     bufs = smem + 3072;

    const int tid = threadIdx.x, warp = tid >> 5, lane = tid & 31;
    const int jw = warp & 7, cw = warp >> 3;
    const int cb = blockIdx.x * 128;
    const int cp = warp;          // loader: c-pair index 0..15
    const int g  = lane;          // loader: px group 0..31

    if (tid < 256) { sc[tid] = 0; rmn[tid] = 0xFFFFFFFFu; rmx[tid] = 0u; }
    __syncthreads();

    // thread-fixed x base: (c = 2*cp, px = cb + 4*g)
    const int gpx = cb + g * 4;
    const int nb  = gpx / HW;
    const int hwx = gpx - nb * HW;
    const float* xt = x + (size_t)nb * CHW + (size_t)(cp * 2) * HW + hwx;

    float acc[2][8][4];
#pragma unroll
    for (int m = 0; m < 2; ++m)
#pragma unroll
        for (int nf = 0; nf < 8; ++nf)
#pragma unroll
            for (int q = 0; q < 4; ++q) acc[m][nf][q] = 0.f;

    float4 xr0, xr1;

    // ---- A issue macro-ish lambdas ----
    auto A_issue = [&](int c4, int buf) {
        const int kc = c4 * 32;
        char* base = bufs + buf * G1_BUF;
#pragma unroll
        for (int i = 0; i < 4; ++i) {
            int idx = tid + i * 512;
            int half = idx >> 10, sub = idx & 1023;
            int row = sub >> 2, seg = sub & 3;
            const __nv_bfloat16* src = (half ? g_utlo : g_uthi) + row * 256 + kc + seg * 8;
            uint32_t dst = (uint32_t)__cvta_generic_to_shared(base + half * 20480 + row * 80 + seg * 16);
            cp16(dst, src);
        }
        asm volatile("cp.async.commit_group;" ::: "memory");
    };
    auto B_sts = [&](int c4, int buf, float4 a, float4 b) {
        const int kc = c4 * 32, c0 = cp * 2;
        unsigned* Bhw = (unsigned*)(bufs + buf * G1_BUF + 40960);
        unsigned* Blw = (unsigned*)(bufs + buf * G1_BUF + 50176);
        float v[4] = {fmaxf(a.x, 0.f), fmaxf(a.y, 0.f), fmaxf(a.z, 0.f), fmaxf(a.w, 0.f)};
        float w[4] = {fmaxf(b.x, 0.f), fmaxf(b.y, 0.f), fmaxf(b.z, 0.f), fmaxf(b.w, 0.f)};
        int s0 = (int)llrintf((v[0] + v[1] + v[2] + v[3]) * 65536.f);
        int s1 = (int)llrintf((w[0] + w[1] + w[2] + w[3]) * 65536.f);
        s0 = __reduce_add_sync(0xffffffffu, s0);
        s1 = __reduce_add_sync(0xffffffffu, s1);
        if (lane == 0) { atomicAdd(&sc[kc + c0], s0); atomicAdd(&sc[kc + c0 + 1], s1); }
#pragma unroll
        for (int q = 0; q < 4; ++q) {
            __nv_bfloat16 h0, l0, h1, l1;
            split_bf16(v[q], h0, l0);
            split_bf16(w[q], h1, l1);
            int r = g * 4 + q;
            int widx = r * 18 + (cp ^ (g & 15));
            Bhw[widx] = pack2(h0, h1);
            Blw[widx] = pack2(l0, l1);
        }
    };

    // prologue: chunk 0
    A_issue(0, 0);
    xr0 = *(const float4*)(xt);
    xr1 = *(const float4*)(xt + HW);
    B_sts(0, 0, xr0, xr1);

#pragma unroll 2
    for (int c4 = 0; c4 < 8; ++c4) {
        const int buf = c4 & 1;
        asm volatile("cp.async.wait_group 0;" ::: "memory");
        __syncthreads();   // A(c4)+B(c4) visible; all mma(c4-1) done
        if (c4 < 7) {
            A_issue(c4 + 1, buf ^ 1);
            xr0 = *(const float4*)(xt + (size_t)(c4 + 1) * 32 * HW);
            xr1 = *(const float4*)(xt + (size_t)(c4 + 1) * 32 * HW + HW);
        }
        // ---- MMA on buf ----
        {
            const __nv_bfloat16* Ah = (const __nv_bfloat16*)(bufs + buf * G1_BUF);
            const __nv_bfloat16* Al = Ah + 10240;
            const unsigned* Bhw = (const unsigned*)(bufs + buf * G1_BUF + 40960);
            const unsigned* Blw = (const unsigned*)(bufs + buf * G1_BUF + 50176);
#pragma unroll
            for (int ks = 0; ks < 2; ++ks) {
                const int kof = ks * 16;
                unsigned afh[2][4], afl[2][4];
#pragma unroll
                for (int m = 0; m < 2; ++m) {
                    int r  = jw * 32 + m * 16 + (lane >> 2);
                    int c0 = kof + (lane & 3) * 2;
                    afh[m][0] = *(const unsigned*)&Ah[r * 40 + c0];
                    afh[m][1] = *(const unsigned*)&Ah[(r + 8) * 40 + c0];
                    afh[m][2] = *(const unsigned*)&Ah[r * 40 + c0 + 8];
                    afh[m][3] = *(const unsigned*)&Ah[(r + 8) * 40 + c0 + 8];
                    afl[m][0] = *(const unsigned*)&Al[r * 40 + c0];
                    afl[m][1] = *(const unsigned*)&Al[(r + 8) * 40 + c0];
                    afl[m][2] = *(const unsigned*)&Al[r * 40 + c0 + 8];
                    afl[m][3] = *(const unsigned*)&Al[(r + 8) * 40 + c0 + 8];
                }
#pragma unroll
                for (int nf = 0; nf < 8; ++nf) {
                    int coln = cw * 64 + nf * 8 + (lane >> 2);
                    int wc   = ks * 8 + (lane & 3);
                    int xo   = (coln >> 2) & 15;
                    int rowb = coln * 18;
                    unsigned bh[2], bl[2];
                    bh[0] = Bhw[rowb + (wc ^ xo)];
                    bh[1] = Bhw[rowb + ((wc + 4) ^ xo)];
                    bl[0] = Blw[rowb + (wc ^ xo)];
                    bl[1] = Blw[rowb + ((wc + 4) ^ xo)];
#pragma unroll
                    for (int m = 0; m < 2; ++m) {
                        mma_bf16(acc[m][nf], afh[m], bh);
                        mma_bf16(acc[m][nf], afh[m], bl);
                        mma_bf16(acc[m][nf], afl[m], bh);
                    }
                }
            }
        }
        if (c4 < 7) B_sts(c4 + 1, buf ^ 1, xr0, xr1);
    }

    // ---- epilogue: per-row min/max, y store ----
#pragma unroll
    for (int m = 0; m < 2; ++m) {
        float mn0 = 3.4e38f, mx0 = -3.4e38f, mn1 = 3.4e38f, mx1 = -3.4e38f;
#pragma unroll
        for (int nf = 0; nf < 8; ++nf) {
            mn0 = fminf(mn0, fminf(acc[m][nf][0], acc[m][nf][1]));
            mx0 = fmaxf(mx0, fmaxf(acc[m][nf][0], acc[m][nf][1]));
            mn1 = fminf(mn1, fminf(acc[m][nf][2], acc[m][nf][3]));
            mx1 = fmaxf(mx1, fmaxf(acc[m][nf][2], acc[m][nf][3]));
        }
        mn0 = fminf(mn0, __shfl_xor_sync(0xffffffffu, mn0, 1));
        mn0 = fminf(mn0, __shfl_xor_sync(0xffffffffu, mn0, 2));
        mx0 = fmaxf(mx0, __shfl_xor_sync(0xffffffffu, mx0, 1));
        mx0 = fmaxf(mx0, __shfl_xor_sync(0xffffffffu, mx0, 2));
        mn1 = fminf(mn1, __shfl_xor_sync(0xffffffffu, mn1, 1));
        mn1 = fminf(mn1, __shfl_xor_sync(0xffffffffu, mn1, 2));
        mx1 = fmaxf(mx1, __shfl_xor_sync(0xffffffffu, mx1, 1));
        mx1 = fmaxf(mx1, __shfl_xor_sync(0xffffffffu, mx1, 2));
        if ((lane & 3) == 0) {
            int r0 = jw * 32 + m * 16 + (lane >> 2);
            atomicMin(&rmn[r0], fkey(mn0));
            atomicMax(&rmx[r0], fkey(mx0));
            atomicMin(&rmn[r0 + 8], fkey(mn1));
            atomicMax(&rmx[r0 + 8], fkey(mx1));
        }
    }
#pragma unroll
    for (int m = 0; m < 2; ++m) {
        int r0 = jw * 32 + m * 16 + (lane >> 2);
#pragma unroll
        for (int nf = 0; nf < 8; ++nf) {
            int coln = cb + cw * 64 + nf * 8 + (lane & 3) * 2;
            *(float2*)&g_y[(size_t)r0 * MDIM + coln] = make_float2(acc[m][nf][0], acc[m][nf][1]);
            *(float2*)&g_y[(size_t)(r0 + 8) * MDIM + coln] = make_float2(acc[m][nf][2], acc[m][nf][3]);
        }
    }
    __syncthreads();
    if (tid < 256) {
        atomicMin(&g_yminK[tid], rmn[tid]);
        atomicMax(&g_ymaxK[tid], rmx[tid]);
        atomicAdd(&g_csum[tid], (unsigned long long)(long long)sc[tid]);
    }
}

// -------- pass 2: mn, s, dmin/scale --------
__global__ void k_prep(const float* __restrict__ u, const float* __restrict__ cl) {
    __shared__ float mn_s[256];
    int j = threadIdx.x;
    float mn = (float)(((double)g_csum[j] * (1.0 / 65536.0)) / (double)MDIM);
    mn_s[j] = mn;
    g_mn[j] = mn;
    __syncthreads();
    float s = 0.f;
    for (int c = 0; c < 256; ++c) s += u[c * 256 + j] * mn_s[c];
    g_s[j] = s;
    float ymin = kinv(g_yminK[j]) - s;
    float ymax = kinv(g_ymaxK[j]) - s;
    float c = cl[j];
    float dmin = fminf(fmaxf(ymin, -c), c);
    float dmax = fminf(fmaxf(ymax, -c), c);
    float rng = dmax - dmin;
    float scale = 255.f / ((rng == 0.f) ? 1.f : rng);
    g_dmin[j]  = dmin;
    g_scale[j] = scale;
    g_inv[j]   = 1.f / scale;
}

// -------- pass 3: quantize 16B/thread; warp-aligned j --------
__global__ __launch_bounds__(512) void k_quant() {
    int unit = blockIdx.x * 512 + threadIdx.x;        // 0..1605631, 16 elems each
    int j = unit / 6272;                               // 6272 units per j row; 6272%32==0
    int off = unit - j * 6272;
    float s = g_s[j], dmin = g_dmin[j], sc = g_scale[j];
    const float4* yp = (const float4*)(g_y + (size_t)j * MDIM + (size_t)off * 16);
    unsigned ob[4];
    int ks = 0;
#pragma unroll
    for (int q = 0; q < 4; ++q) {
        float4 y = yp[q];
        int k0 = (int)fminf(fmaxf(rintf((y.x - s - dmin) * sc), 0.f), 255.f);
        int k1 = (int)fminf(fmaxf(rintf((y.y - s - dmin) * sc), 0.f), 255.f);
        int k2 = (int)fminf(fmaxf(rintf((y.z - s - dmin) * sc), 0.f), 255.f);
        int k3 = (int)fminf(fmaxf(rintf((y.w - s - dmin) * sc), 0.f), 255.f);
        ob[q] = (unsigned)k0 | ((unsigned)k1 << 8) | ((unsigned)k2 << 16) | ((unsigned)k3 << 24);
        ks += k0 + k1 + k2 + k3;
    }
    *(uint4*)(g_k + (size_t)j * MDIM + (size_t)off * 16) = make_uint4(ob[0], ob[1], ob[2], ob[3]);
    ks = __reduce_add_sync(0xffffffffu, ks);
    if ((threadIdx.x & 31) == 0) atomicAdd(&g_ksum[j], ks);
}

// -------- pass 4: u' = u*inv split hi/lo, beta --------
__global__ void k_prep2(const float* __restrict__ u) {
    __shared__ float red[256];
    int i = blockIdx.x, j = threadIdx.x;
    float v = u[i * 256 + j] * g_inv[j];
    split_bf16(v, g_uphi[i * 256 + j], g_uplo[i * 256 + j]);
    float meank = (float)g_ksum[j] / (float)MDIM;
    red[j] = v * meank;
    __syncthreads();
    for (int sN = 128; sN > 0; sN >>= 1) {
        if (j < sN) red[j] += red[j + sN];
        __syncthreads();
    }
    if (j == 0) g_beta[i] = g_mn[i] - red[0];
}

// ==================== GEMM2: out = u' @ k + beta (NCHW) ====================
#define G2_BUF 50176
__global__ __launch_bounds__(512, 1) void k_gemm2(float* __restrict__ out) {
    extern __shared__ __align__(16) char smem[];
    float* sbeta = (float*)smem;
    char*  bufs  = smem + 1024;

    const int tid = threadIdx.x, warp = tid >> 5, lane = tid & 31;
    const int jw = warp & 7, cw = warp >> 3;
    const int cb = blockIdx.x * 128;
    const int cp = warp, g = lane;

    if (tid < 256) sbeta[tid] = g_beta[tid];
    __syncthreads();

    const unsigned char* kt = g_k + (size_t)(cp * 2) * MDIM + cb + g * 4;

    float acc[2][8][4];
#pragma unroll
    for (int m = 0; m < 2; ++m)
#pragma unroll
        for (int nf = 0; nf < 8; ++nf)
#pragma unroll
            for (int q = 0; q < 4; ++q) acc[m][nf][q] = 0.f;

    unsigned kr0, kr1;

    auto A_issue = [&](int c4, int buf) {
        const int kc = c4 * 32;
        char* base = bufs + buf * G2_BUF;
#pragma unroll
        for (int i = 0; i < 4; ++i) {
            int idx = tid + i * 512;
            int half = idx >> 10, sub = idx & 1023;
            int row = sub >> 2, seg = sub & 3;
            const __nv_bfloat16* src = (half ? g_uplo : g_uphi) + row * 256 + kc + seg * 8;
            uint32_t dst = (uint32_t)__cvta_generic_to_shared(base + half * 20480 + row * 80 + seg * 16);
            cp16(dst, src);
        }
        asm volatile("cp.async.commit_group;" ::: "memory");
    };
    auto B_sts = [&](int buf, unsigned a, unsigned b) {
        unsigned* Bw = (unsigned*)(bufs + buf * G2_BUF + 40960);
#pragma unroll
        for (int q = 0; q < 4; ++q) {
            __nv_bfloat16 h0 = __float2bfloat16((float)((a >> (q * 8)) & 255u));
            __nv_bfloat16 h1 = __float2bfloat16((float)((b >> (q * 8)) & 255u));
            int r = g * 4 + q;
            Bw[r * 18 + (cp ^ (g & 15))] = pack2(h0, h1);
        }
    };

    A_issue(0, 0);
    kr0 = *(const unsigned*)(kt);
    kr1 = *(const unsigned*)(kt + MDIM);
    B_sts(0, kr0, kr1);

#pragma unroll 2
    for (int c4 = 0; c4 < 8; ++c4) {
        const int buf = c4 & 1;
        asm volatile("cp.async.wait_group 0;" ::: "memory");
        __syncthreads();
        if (c4 < 7) {
            A_issue(c4 + 1, buf ^ 1);
            kr0 = *(const unsigned*)(kt + (size_t)(c4 + 1) * 32 * MDIM);
            kr1 = *(const unsigned*)(kt + (size_t)(c4 + 1) * 32 * MDIM + MDIM);
        }
        {
            const __nv_bfloat16* Ah = (const __nv_bfloat16*)(bufs + buf * G2_BUF);
            const __nv_bfloat16* Al = Ah + 10240;
            const unsigned* Bw = (const unsigned*)(bufs + buf * G2_BUF + 40960);
#pragma unroll
            for (int ks = 0; ks < 2; ++ks) {
                const int kof = ks * 16;
                unsigned afh[2][4], afl[2][4];
#pragma unroll
                for (int m = 0; m < 2; ++m) {
                    int r  = jw * 32 + m * 16 + (lane >> 2);
                    int c0 = kof + (lane & 3) * 2;
                    afh[m][0] = *(const unsigned*)&Ah[r * 40 + c0];
                    afh[m][1] = *(const unsigned*)&Ah[(r + 8) * 40 + c0];
                    afh[m][2] = *(const unsigned*)&Ah[r * 40 + c0 + 8];
                    afh[m][3] = *(const unsigned*)&Ah[(r + 8) * 40 + c0 + 8];
                    afl[m][0] = *(const unsigned*)&Al[r * 40 + c0];
                    afl[m][1] = *(const unsigned*)&Al[(r + 8) * 40 + c0];
                    afl[m][2] = *(const unsigned*)&Al[r * 40 + c0 + 8];
                    afl[m][3] = *(const unsigned*)&Al[(r + 8) * 40 + c0 + 8];
                }
#pragma unroll
                for (int nf = 0; nf < 8; ++nf) {
                    int coln = cw * 64 + nf * 8 + (lane >> 2);
                    int wc   = ks * 8 + (lane & 3);
                    int xo   = (coln >> 2) & 15;
                    int rowb = coln * 18;
                    unsigned b[2];
                    b[0] = Bw[rowb + (wc ^ xo)];
                    b[1] = Bw[rowb + ((wc + 4) ^ xo)];
#pragma unroll
                    for (int m = 0; m < 2; ++m) {
                        mma_bf16(acc[m][nf], afh[m], b);
                        mma_bf16(acc[m][nf], afl[m], b);
                    }
                }
            }
        }
        if (c4 < 7) B_sts(buf ^ 1, kr0, kr1);
    }

    // epilogue: add beta, store NCHW
#pragma unroll
    for (int m = 0; m < 2; ++m) {
        int r0 = jw * 32 + m * 16 + (lane >> 2);
        float b0 = sbeta[r0], b1 = sbeta[r0 + 8];
#pragma unroll
        for (int nf = 0; nf < 8; ++nf) {
            int col = cb + cw * 64 + nf * 8 + (lane & 3) * 2;
            int n = col / HW, hw2 = col - n * HW;
            *(float2*)&out[(size_t)n * CHW + (size_t)r0 * HW + hw2] =
                make_float2(acc[m][nf][0] + b0, acc[m][nf][1] + b0);
            *(float2*)&out[(size_t)n * CHW + (size_t)(r0 + 8) * HW + hw2] =
                make_float2(acc[m][nf][2] + b1, acc[m][nf][3] + b1);
        }
    }
}

extern "C" void kernel_launch(void* const* d_in, const int* in_sizes, int n_in,
                              void* d_out, int out_size) {
    const float* x  = (const float*)d_in[0];
    const float* u  = (const float*)d_in[1];
    const float* cl = (const float*)d_in[2];
    float* out = (float*)d_out;

    cudaFuncSetAttribute(k_gemm1, cudaFuncAttributeMaxDynamicSharedMemorySize, 3072 + 2 * G1_BUF);
    cudaFuncSetAttribute(k_gemm2, cudaFuncAttributeMaxDynamicSharedMemorySize, 1024 + 2 * G2_BUF);

    k_init <<<1, 256>>>();
    k_prep0<<<256, 256>>>(u);
    k_gemm1<<<784, 512, 3072 + 2 * G1_BUF>>>(x);
    k_prep <<<1, 256>>>(u, cl);
    k_quant<<<3136, 512>>>();
    k_prep2<<<256, 256>>>(u);
    k_gemm2<<<784, 512, 1024 + 2 * G2_BUF>>>(out);
}

// round 4
// speedup vs baseline: 1.7258x; 1.0401x over previous
#include <cuda_runtime.h>
#include <cuda_bf16.h>
#include <cstdint>

#define HW   3136
#define CHW  802816
#define MDIM 100352   // 32*56*56

// ---------------- scratch (no cudaMalloc allowed) ----------------
__device__ float              g_y[(size_t)256 * MDIM];
__device__ unsigned char      g_k[(size_t)256 * MDIM];
__device__ unsigned long long g_csum[256];
__device__ unsigned           g_yminK[256];
__device__ unsigned           g_ymaxK[256];
__device__ int                g_ksum[256];
__device__ float g_mn[256], g_s[256], g_dmin[256], g_scale[256], g_inv[256], g_beta[256];
__device__ __nv_bfloat16 g_uphi[65536], g_uplo[65536];   // u' = u*inv  [i][j]
__device__ __nv_bfloat16 g_uthi[65536], g_utlo[65536];   // u^T         [j][c]

// ---------------- helpers ----------------
static __device__ __forceinline__ unsigned fkey(float f) {
    unsigned u = __float_as_uint(f);
    return (u & 0x80000000u) ? ~u : (u | 0x80000000u);
}
static __device__ __forceinline__ float kinv(unsigned k) {
    unsigned u = (k & 0x80000000u) ? (k & 0x7fffffffu) : ~k;
    return __uint_as_float(u);
}
static __device__ __forceinline__ void split_bf16(float v, __nv_bfloat16& hi, __nv_bfloat16& lo) {
    hi = __float2bfloat16(v);
    lo = __float2bfloat16(v - __bfloat162float(hi));
}
static __device__ __forceinline__ void mma_bf16(float d[4], const unsigned a[4], const unsigned b[2]) {
    asm volatile(
        "mma.sync.aligned.m16n8k16.row.col.f32.bf16.bf16.f32 "
        "{%0,%1,%2,%3},{%4,%5,%6,%7},{%8,%9},{%0,%1,%2,%3};"
        : "+f"(d[0]), "+f"(d[1]), "+f"(d[2]), "+f"(d[3])
        : "r"(a[0]), "r"(a[1]), "r"(a[2]), "r"(a[3]), "r"(b[0]), "r"(b[1]));
}
static __device__ __forceinline__ void ldm4(unsigned r[4], uint32_t addr) {
    asm volatile("ldmatrix.sync.aligned.m8n8.x4.shared.b16 {%0,%1,%2,%3}, [%4];"
        : "=r"(r[0]), "=r"(r[1]), "=r"(r[2]), "=r"(r[3]) : "r"(addr));
}
static __device__ __forceinline__ void cp16(uint32_t dst, const void* src) {
    asm volatile("cp.async.cg.shared.global [%0],[%1],16;" :: "r"(dst), "l"(src));
}
static __device__ __forceinline__ unsigned pack2(__nv_bfloat16 a, __nv_bfloat16 b) {
    return (unsigned)__bfloat16_as_ushort(a) | ((unsigned)__bfloat16_as_ushort(b) << 16);
}

// -------- pass 0: init accumulators + u^T hi/lo split --------
__global__ void k_prep0(const float* __restrict__ u) {
    int j = blockIdx.x, c = threadIdx.x;
    if (j == 0) {
        g_csum[c]  = 0ull;
        g_yminK[c] = 0xFFFFFFFFu;
        g_ymaxK[c] = 0u;
        g_ksum[c]  = 0;
    }
    float v = u[c * 256 + j];
    split_bf16(v, g_uthi[j * 256 + c], g_utlo[j * 256 + c]);
}

// ==================== GEMM1: y = u^T @ relu(x) ====================
// CTA: M=256 (all j), N=128 px, K=256 in 8 chunks of 32. 512 threads = 16 warps.
#define G1_BUF 59392
__global__ __launch_bounds__(512, 1) void k_gemm1(const float* __restrict__ x) {
    extern __shared__ __align__(16) char smem[];
    int*      sc  = (int*)smem;
    unsigned* rmn = (unsigned*)(smem + 1024);
    unsigned* rmx = (unsigned*)(smem + 2048);
    char*     bufs = smem + 3072;

    const int tid = threadIdx.x, warp = tid >> 5, lane = tid & 31;
    const int jw = warp & 7, cw = warp >> 3;
    const int cb = blockIdx.x * 128;
    const int cp = warp;          // loader: c-pair index 0..15
    const int g  = lane;          // loader: px group 0..31

    if (tid < 256) { sc[tid] = 0; rmn[tid] = 0xFFFFFFFFu; rmx[tid] = 0u; }
    __syncthreads();

    const int gpx = cb + g * 4;
    const int nb  = gpx / HW;
    const int hwx = gpx - nb * HW;
    const float* xt = x + (size_t)nb * CHW + (size_t)(cp * 2) * HW + hwx;

    // ldmatrix lane-fixed A offsets
    const uint32_t bufs0 = (uint32_t)__cvta_generic_to_shared(bufs);
    const uint32_t aoff = (uint32_t)((jw * 32 + (lane & 7) + ((lane >> 3) & 1) * 8) * 80
                                     + ((lane >> 4) & 1) * 16);

    float acc[2][8][4];
#pragma unroll
    for (int m = 0; m < 2; ++m)
#pragma unroll
        for (int nf = 0; nf < 8; ++nf)
#pragma unroll
            for (int q = 0; q < 4; ++q) acc[m][nf][q] = 0.f;

    float4 xr0, xr1;

    auto A_issue = [&](int c4, int buf) {
        const int kc = c4 * 32;
        char* base = bufs + buf * G1_BUF;
#pragma unroll
        for (int i = 0; i < 4; ++i) {
            int idx = tid + i * 512;
            int half = idx >> 10, sub = idx & 1023;
            int row = sub >> 2, seg = sub & 3;
            const __nv_bfloat16* src = (half ? g_utlo : g_uthi) + row * 256 + kc + seg * 8;
            uint32_t dst = (uint32_t)__cvta_generic_to_shared(base + half * 20480 + row * 80 + seg * 16);
            cp16(dst, src);
        }
        asm volatile("cp.async.commit_group;" ::: "memory");
    };
    auto B_sts = [&](int c4, int buf, float4 a, float4 b) {
        const int kc = c4 * 32, c0 = cp * 2;
        unsigned* Bhw = (unsigned*)(bufs + buf * G1_BUF + 40960);
        unsigned* Blw = (unsigned*)(bufs + buf * G1_BUF + 50176);
        float v[4] = {fmaxf(a.x, 0.f), fmaxf(a.y, 0.f), fmaxf(a.z, 0.f), fmaxf(a.w, 0.f)};
        float w[4] = {fmaxf(b.x, 0.f), fmaxf(b.y, 0.f), fmaxf(b.z, 0.f), fmaxf(b.w, 0.f)};
        int s0 = (int)llrintf((v[0] + v[1] + v[2] + v[3]) * 65536.f);
        int s1 = (int)llrintf((w[0] + w[1] + w[2] + w[3]) * 65536.f);
        s0 = __reduce_add_sync(0xffffffffu, s0);
        s1 = __reduce_add_sync(0xffffffffu, s1);
        if (lane == 0) { atomicAdd(&sc[kc + c0], s0); atomicAdd(&sc[kc + c0 + 1], s1); }
#pragma unroll
        for (int q = 0; q < 4; ++q) {
            __nv_bfloat16 h0, l0, h1, l1;
            split_bf16(v[q], h0, l0);
            split_bf16(w[q], h1, l1);
            int r = g * 4 + q;
            int widx = r * 18 + (cp ^ (g & 15));
            Bhw[widx] = pack2(h0, h1);
            Blw[widx] = pack2(l0, l1);
        }
    };

    A_issue(0, 0);
    xr0 = *(const float4*)(xt);
    xr1 = *(const float4*)(xt + HW);
    B_sts(0, 0, xr0, xr1);

#pragma unroll 2
    for (int c4 = 0; c4 < 8; ++c4) {
        const int buf = c4 & 1;
        asm volatile("cp.async.wait_group 0;" ::: "memory");
        __syncthreads();
        if (c4 < 7) {
            A_issue(c4 + 1, buf ^ 1);
            xr0 = *(const float4*)(xt + (size_t)(c4 + 1) * 32 * HW);
            xr1 = *(const float4*)(xt + (size_t)(c4 + 1) * 32 * HW + HW);
        }
        {
            const uint32_t Ab = bufs0 + buf * G1_BUF + aoff;
            const unsigned* Bhw = (const unsigned*)(bufs + buf * G1_BUF + 40960);
            const unsigned* Blw = (const unsigned*)(bufs + buf * G1_BUF + 50176);
#pragma unroll
            for (int ks = 0; ks < 2; ++ks) {
                unsigned afh[2][4], afl[2][4];
#pragma unroll
                for (int m = 0; m < 2; ++m) {
                    ldm4(afh[m], Ab + m * 1280 + ks * 32);
                    ldm4(afl[m], Ab + 20480u + m * 1280 + ks * 32);
                }
#pragma unroll
                for (int nf = 0; nf < 8; ++nf) {
                    int coln = cw * 64 + nf * 8 + (lane >> 2);
                    int wc   = ks * 8 + (lane & 3);
                    int xo   = (coln >> 2) & 15;
                    int rowb = coln * 18;
                    unsigned bh[2], bl[2];
                    bh[0] = Bhw[rowb + (wc ^ xo)];
                    bh[1] = Bhw[rowb + ((wc + 4) ^ xo)];
                    bl[0] = Blw[rowb + (wc ^ xo)];
                    bl[1] = Blw[rowb + ((wc + 4) ^ xo)];
#pragma unroll
                    for (int m = 0; m < 2; ++m) {
                        mma_bf16(acc[m][nf], afh[m], bh);
                        mma_bf16(acc[m][nf], afh[m], bl);
                        mma_bf16(acc[m][nf], afl[m], bh);
                    }
                }
            }
        }
        if (c4 < 7) B_sts(c4 + 1, buf ^ 1, xr0, xr1);
    }

    // ---- epilogue: per-row min/max, y store ----
#pragma unroll
    for (int m = 0; m < 2; ++m) {
        float mn0 = 3.4e38f, mx0 = -3.4e38f, mn1 = 3.4e38f, mx1 = -3.4e38f;
#pragma unroll
        for (int nf = 0; nf < 8; ++nf) {
            mn0 = fminf(mn0, fminf(acc[m][nf][0], acc[m][nf][1]));
            mx0 = fmaxf(mx0, fmaxf(acc[m][nf][0], acc[m][nf][1]));
            mn1 = fminf(mn1, fminf(acc[m][nf][2], acc[m][nf][3]));
            mx1 = fmaxf(mx1, fmaxf(acc[m][nf][2], acc[m][nf][3]));
        }
        mn0 = fminf(mn0, __shfl_xor_sync(0xffffffffu, mn0, 1));
        mn0 = fminf(mn0, __shfl_xor_sync(0xffffffffu, mn0, 2));
        mx0 = fmaxf(mx0, __shfl_xor_sync(0xffffffffu, mx0, 1));
        mx0 = fmaxf(mx0, __shfl_xor_sync(0xffffffffu, mx0, 2));
        mn1 = fminf(mn1, __shfl_xor_sync(0xffffffffu, mn1, 1));
        mn1 = fminf(mn1, __shfl_xor_sync(0xffffffffu, mn1, 2));
        mx1 = fmaxf(mx1, __shfl_xor_sync(0xffffffffu, mx1, 1));
        mx1 = fmaxf(mx1, __shfl_xor_sync(0xffffffffu, mx1, 2));
        if ((lane & 3) == 0) {
            int r0 = jw * 32 + m * 16 + (lane >> 2);
            atomicMin(&rmn[r0], fkey(mn0));
            atomicMax(&rmx[r0], fkey(mx0));
            atomicMin(&rmn[r0 + 8], fkey(mn1));
            atomicMax(&rmx[r0 + 8], fkey(mx1));
        }
    }
#pragma unroll
    for (int m = 0; m < 2; ++m) {
        int r0 = jw * 32 + m * 16 + (lane >> 2);
#pragma unroll
        for (int nf = 0; nf < 8; ++nf) {
            int coln = cb + cw * 64 + nf * 8 + (lane & 3) * 2;
            *(float2*)&g_y[(size_t)r0 * MDIM + coln] = make_float2(acc[m][nf][0], acc[m][nf][1]);
            *(float2*)&g_y[(size_t)(r0 + 8) * MDIM + coln] = make_float2(acc[m][nf][2], acc[m][nf][3]);
        }
    }
    __syncthreads();
    if (tid < 256) {
        atomicMin(&g_yminK[tid], rmn[tid]);
        atomicMax(&g_ymaxK[tid], rmx[tid]);
        atomicAdd(&g_csum[tid], (unsigned long long)(long long)sc[tid]);
    }
}

// -------- pass 2a: mn --------
__global__ void k_prepA() {
    int j = threadIdx.x;
    g_mn[j] = (float)(((double)g_csum[j] * (1.0 / 65536.0)) / (double)MDIM);
}
// -------- pass 2b: s[j], dmin/scale/inv (block j) --------
__global__ void k_prepS(const float* __restrict__ cl) {
    __shared__ float wred[8];
    int j = blockIdx.x, c = threadIdx.x;
    int lane = c & 31, warp = c >> 5;
    float uv = __bfloat162float(g_uthi[j * 256 + c]) + __bfloat162float(g_utlo[j * 256 + c]);
    float p = uv * g_mn[c];
#pragma unroll
    for (int off = 16; off > 0; off >>= 1) p += __shfl_down_sync(0xffffffffu, p, off);
    if (lane == 0) wred[warp] = p;
    __syncthreads();
    if (c == 0) {
        float s = 0.f;
#pragma unroll
        for (int i = 0; i < 8; ++i) s += wred[i];
        g_s[j] = s;
        float ymin = kinv(g_yminK[j]) - s;
        float ymax = kinv(g_ymaxK[j]) - s;
        float cc = cl[j];
        float dmin = fminf(fmaxf(ymin, -cc), cc);
        float dmax = fminf(fmaxf(ymax, -cc), cc);
        float rng = dmax - dmin;
        float scale = 255.f / ((rng == 0.f) ? 1.f : rng);
        g_dmin[j]  = dmin;
        g_scale[j] = scale;
        g_inv[j]   = 1.f / scale;
    }
}

// -------- pass 3: quantize 16B/thread; warp-aligned j --------
__global__ __launch_bounds__(512) void k_quant() {
    int unit = blockIdx.x * 512 + threadIdx.x;
    int j = unit / 6272;
    int off = unit - j * 6272;
    float s = g_s[j], dmin = g_dmin[j], sc = g_scale[j];
    const float4* yp = (const float4*)(g_y + (size_t)j * MDIM + (size_t)off * 16);
    unsigned ob[4];
    int ks = 0;
#pragma unroll
    for (int q = 0; q < 4; ++q) {
        float4 y = yp[q];
        int k0 = (int)fminf(fmaxf(rintf((y.x - s - dmin) * sc), 0.f), 255.f);
        int k1 = (int)fminf(fmaxf(rintf((y.y - s - dmin) * sc), 0.f), 255.f);
        int k2 = (int)fminf(fmaxf(rintf((y.z - s - dmin) * sc), 0.f), 255.f);
        int k3 = (int)fminf(fmaxf(rintf((y.w - s - dmin) * sc), 0.f), 255.f);
        ob[q] = (unsigned)k0 | ((unsigned)k1 << 8) | ((unsigned)k2 << 16) | ((unsigned)k3 << 24);
        ks += k0 + k1 + k2 + k3;
    }
    *(uint4*)(g_k + (size_t)j * MDIM + (size_t)off * 16) = make_uint4(ob[0], ob[1], ob[2], ob[3]);
    ks = __reduce_add_sync(0xffffffffu, ks);
    if ((threadIdx.x & 31) == 0) atomicAdd(&g_ksum[j], ks);
}

// -------- pass 4: u' = u*inv split hi/lo, beta --------
__global__ void k_prep2(const float* __restrict__ u) {
    __shared__ float red[256];
    int i = blockIdx.x, j = threadIdx.x;
    float v = u[i * 256 + j] * g_inv[j];
    split_bf16(v, g_uphi[i * 256 + j], g_uplo[i * 256 + j]);
    float meank = (float)g_ksum[j] / (float)MDIM;
    red[j] = v * meank;
    __syncthreads();
    for (int sN = 128; sN > 0; sN >>= 1) {
        if (j < sN) red[j] += red[j + sN];
        __syncthreads();
    }
    if (j == 0) g_beta[i] = g_mn[i] - red[0];
}

// ==================== GEMM2: out = u' @ k + beta (NCHW) ====================
#define G2_BUF 50176
__global__ __launch_bounds__(512, 1) void k_gemm2(float* __restrict__ out) {
    extern __shared__ __align__(16) char smem[];
    float* sbeta = (float*)smem;
    char*  bufs  = smem + 1024;

    const int tid = threadIdx.x, warp = tid >> 5, lane = tid & 31;
    const int jw = warp & 7, cw = warp >> 3;
    const int cb = blockIdx.x * 128;
    const int cp = warp, g = lane;

    if (tid < 256) sbeta[tid] = g_beta[tid];
    __syncthreads();

    const unsigned char* kt = g_k + (size_t)(cp * 2) * MDIM + cb + g * 4;

    const uint32_t bufs0 = (uint32_t)__cvta_generic_to_shared(bufs);
    const uint32_t aoff = (uint32_t)((jw * 32 + (lane & 7) + ((lane >> 3) & 1) * 8) * 80
                                     + ((lane >> 4) & 1) * 16);

    float acc[2][8][4];
#pragma unroll
    for (int m = 0; m < 2; ++m)
#pragma unroll
        for (int nf = 0; nf < 8; ++nf)
#pragma unroll
            for (int q = 0; q < 4; ++q) acc[m][nf][q] = 0.f;

    unsigned kr0, kr1;

    auto A_issue = [&](int c4, int buf) {
        const int kc = c4 * 32;
        char* base = bufs + buf * G2_BUF;
#pragma unroll
        for (int i = 0; i < 4; ++i) {
            int idx = tid + i * 512;
            int half = idx >> 10, sub = idx & 1023;
            int row = sub >> 2, seg = sub & 3;
            const __nv_bfloat16* src = (half ? g_uplo : g_uphi) + row * 256 + kc + seg * 8;
            uint32_t dst = (uint32_t)__cvta_generic_to_shared(base + half * 20480 + row * 80 + seg * 16);
            cp16(dst, src);
        }
        asm volatile("cp.async.commit_group;" ::: "memory");
    };
    auto B_sts = [&](int buf, unsigned a, unsigned b) {
        unsigned* Bw = (unsigned*)(bufs + buf * G2_BUF + 40960);
#pragma unroll
        for (int q = 0; q < 4; ++q) {
            __nv_bfloat16 h0 = __float2bfloat16((float)((a >> (q * 8)) & 255u));
            __nv_bfloat16 h1 = __float2bfloat16((float)((b >> (q * 8)) & 255u));
            int r = g * 4 + q;
            Bw[r * 18 + (cp ^ (g & 15))] = pack2(h0, h1);
        }
    };

    A_issue(0, 0);
    kr0 = *(const unsigned*)(kt);
    kr1 = *(const unsigned*)(kt + MDIM);
    B_sts(0, kr0, kr1);

#pragma unroll 2
    for (int c4 = 0; c4 < 8; ++c4) {
        const int buf = c4 & 1;
        asm volatile("cp.async.wait_group 0;" ::: "memory");
        __syncthreads();
        if (c4 < 7) {
            A_issue(c4 + 1, buf ^ 1);
            kr0 = *(const unsigned*)(kt + (size_t)(c4 + 1) * 32 * MDIM);
            kr1 = *(const unsigned*)(kt + (size_t)(c4 + 1) * 32 * MDIM + MDIM);
        }
        {
            const uint32_t Ab = bufs0 + buf * G2_BUF + aoff;
            const unsigned* Bw = (const unsigned*)(bufs + buf * G2_BUF + 40960);
#pragma unroll
            for (int ks = 0; ks < 2; ++ks) {
                unsigned afh[2][4], afl[2][4];
#pragma unroll
                for (int m = 0; m < 2; ++m) {
                    ldm4(afh[m], Ab + m * 1280 + ks * 32);
                    ldm4(afl[m], Ab + 20480u + m * 1280 + ks * 32);
                }
#pragma unroll
                for (int nf = 0; nf < 8; ++nf) {
                    int coln = cw * 64 + nf * 8 + (lane >> 2);
                    int wc   = ks * 8 + (lane & 3);
                    int xo   = (coln >> 2) & 15;
                    int rowb = coln * 18;
                    unsigned b[2];
                    b[0] = Bw[rowb + (wc ^ xo)];
                    b[1] = Bw[rowb + ((wc + 4) ^ xo)];
#pragma unroll
                    for (int m = 0; m < 2; ++m) {
                        mma_bf16(acc[m][nf], afh[m], b);
                        mma_bf16(acc[m][nf], afl[m], b);
                    }
                }
            }
        }
        if (c4 < 7) B_sts(buf ^ 1, kr0, kr1);
    }

#pragma unroll
    for (int m = 0; m < 2; ++m) {
        int r0 = jw * 32 + m * 16 + (lane >> 2);
        float b0 = sbeta[r0], b1 = sbeta[r0 + 8];
#pragma unroll
        for (int nf = 0; nf < 8; ++nf) {
            int col = cb + cw * 64 + nf * 8 + (lane & 3) * 2;
            int n = col / HW, hw2 = col - n * HW;
            *(float2*)&out[(size_t)n * CHW + (size_t)r0 * HW + hw2] =
                make_float2(acc[m][nf][0] + b0, acc[m][nf][1] + b0);
            *(float2*)&out[(size_t)n * CHW + (size_t)(r0 + 8) * HW + hw2] =
                make_float2(acc[m][nf][2] + b1, acc[m][nf][3] + b1);
        }
    }
}

extern "C" void kernel_launch(void* const* d_in, const int* in_sizes, int n_in,
                              void* d_out, int out_size) {
    const float* x  = (const float*)d_in[0];
    const float* u  = (const float*)d_in[1];
    const float* cl = (const float*)d_in[2];
    float* out = (float*)d_out;

    cudaFuncSetAttribute(k_gemm1, cudaFuncAttributeMaxDynamicSharedMemorySize, 3072 + 2 * G1_BUF);
    cudaFuncSetAttribute(k_gemm2, cudaFuncAttributeMaxDynamicSharedMemorySize, 1024 + 2 * G2_BUF);

    k_prep0<<<256, 256>>>(u);
    k_gemm1<<<784, 512, 3072 + 2 * G1_BUF>>>(x);
    k_prepA<<<1, 256>>>();
    k_prepS<<<256, 256>>>(cl);
    k_quant<<<3136, 512>>>();
    k_prep2<<<256, 256>>>(u);
    k_gemm2<<<784, 512, 1024 + 2 * G2_BUF>>>(out);
}